// round 6
// baseline (speedup 1.0000x reference)
#include <cuda_runtime.h>
#include <cuda_bf16.h>
#include <cstdint>
#include <cstddef>

#define SZ 4096
#define NROWS 8192

// -------- scratch (allocation-free rule: static __device__ arrays) --------
__device__ __nv_bfloat16 g_Xhi[(size_t)NROWS * SZ];   // 64 MB
__device__ __nv_bfloat16 g_Xlo[(size_t)NROWS * SZ];   // 64 MB
__device__ __nv_bfloat16 g_Gthi[(size_t)SZ * SZ];     // 32 MB  (transposed: [n][m])
__device__ __nv_bfloat16 g_Gtlo[(size_t)SZ * SZ];     // 32 MB

// ---------------- helpers ----------------
__device__ __forceinline__ uint32_t smem_u32(const void* p) {
    uint32_t a;
    asm("{ .reg .u64 t; cvta.to.shared.u64 t, %1; cvt.u32.u64 %0, t; }" : "=r"(a) : "l"(p));
    return a;
}
__device__ __forceinline__ uint32_t swz(uint32_t o) { return o ^ ((o >> 3) & 0x70); }

__device__ __forceinline__ void cp16(uint32_t dst, const void* src) {
    asm volatile("cp.async.cg.shared.global [%0], [%1], 16;" :: "r"(dst), "l"(src));
}

// ldmatrix x4 (non-transposed), base-arch PTX (sm_75+)
#define LDSM4(r, addr)                                                             \
    asm volatile("ldmatrix.sync.aligned.m8n8.x4.shared.b16 {%0,%1,%2,%3}, [%4];"   \
                 : "=r"((r)[0]), "=r"((r)[1]), "=r"((r)[2]), "=r"((r)[3])          \
                 : "r"(addr))

// mma.sync m16n8k16 row.col f32.bf16.bf16.f32, base-arch PTX (sm_80+)
#define MMA16816(c, a, b0, b1)                                                     \
    asm volatile("mma.sync.aligned.m16n8k16.row.col.f32.bf16.bf16.f32 "            \
                 "{%0,%1,%2,%3}, {%4,%5,%6,%7}, {%8,%9}, {%0,%1,%2,%3};"           \
                 : "+f"((c)[0]), "+f"((c)[1]), "+f"((c)[2]), "+f"((c)[3])          \
                 : "r"((a)[0]), "r"((a)[1]), "r"((a)[2]), "r"((a)[3]),             \
                   "r"(b0), "r"(b1))

// lane address for ldmatrix.x4 covering a 16(row)x16(col-bf16) region at
// (row0, kbyte0) inside a tile whose rows are 128B wide, SW128-swizzled.
// Matrix order: (r0..7,k0..7)(r8..15,k0..7)(r0..7,k8..15)(r8..15,k8..15)
// -> exactly the a0..a3 / b-pair ordering mma.sync expects.
__device__ __forceinline__ uint32_t lm_addr(uint32_t base, int lane, int row0, int kbyte0) {
    const int r = row0 + (lane & 7) + ((lane >> 3) & 1) * 8;
    const int kb = kbyte0 + ((lane >> 4) << 4);     // +16B for the second k-half
    return base + (uint32_t)(r * 128) + (uint32_t)(kb ^ ((r & 7) << 4));
}

// ================= kernel 1: build G (row-wise), store transposed bf16 hi/lo ==
// G[m, n = y*256 + x*16 + z] = sum_B c2[m,z,B] * sum_b c1[m,x,B,b] * c0[m,y,b]
__global__ __launch_bounds__(256) void build_gt(const float* __restrict__ core0,
                                                const float* __restrict__ core1,
                                                const float* __restrict__ core2) {
    __shared__ float c0s[128], c2s[128], c1s[1024];
    const int m = blockIdx.x;
    const int tid = threadIdx.x;
    if (tid < 128) {
        c0s[tid] = core0[m * 128 + tid];
        c2s[tid] = core2[m * 128 + tid];
    }
#pragma unroll
    for (int j = 0; j < 4; j++) c1s[tid + j * 256] = core1[m * 1024 + tid + j * 256];
    __syncthreads();

    const int y = tid >> 4, x = tid & 15;
    float a[8], Mr[8];
#pragma unroll
    for (int b = 0; b < 8; b++) a[b] = c0s[y * 8 + b];
#pragma unroll
    for (int B = 0; B < 8; B++) {
        float s = 0.f;
#pragma unroll
        for (int b = 0; b < 8; b++) s += c1s[x * 64 + B * 8 + b] * a[b];
        Mr[B] = s;
    }
#pragma unroll
    for (int z = 0; z < 16; z++) {
        float v = 0.f;
#pragma unroll
        for (int B = 0; B < 8; B++) v += Mr[B] * c2s[z * 8 + B];
        const int n = y * 256 + x * 16 + z;
        const __nv_bfloat16 h = __float2bfloat16(v);
        const __nv_bfloat16 l = __float2bfloat16(v - __bfloat162float(h));
        const size_t o = (size_t)n * SZ + m;   // transposed store: Gt[n][m]
        g_Gthi[o] = h;
        g_Gtlo[o] = l;
    }
}

// ================= kernel 2: split X into bf16 hi/lo =================
__global__ __launch_bounds__(256) void split_x(const float* __restrict__ x) {
    const size_t i = (size_t)blockIdx.x * 256 + threadIdx.x;
    if (i >= (size_t)NROWS * SZ) return;
    const float v = x[i];
    const __nv_bfloat16 h = __float2bfloat16(v);
    g_Xhi[i] = h;
    g_Xlo[i] = __float2bfloat16(v - __bfloat162float(h));
}

// ================= kernel 3: split-bf16 mma.sync GEMM + bias =================
// out[8192,4096] = Xhi@Ghi + Xhi@Glo + Xlo@Ghi + bias   (fp32 register accum)
// CTA tile 128x128, BK=64, 3-stage cp.async pipeline, SW128 swizzle.
#define STAGE_BYTES 65536
#define OFF_AHI 0
#define OFF_ALO 16384
#define OFF_BHI 32768
#define OFF_BLO 49152
#define NSTAGES 3
#define SM_TOTAL (NSTAGES * STAGE_BYTES)
#define NKITERS 64   // 4096 / 64

__device__ __forceinline__ void issue_stage(uint32_t sb, int stage, int kc,
                                            int m0, int n0, int tid) {
    const uint32_t base = sb + (uint32_t)stage * STAGE_BYTES;
    const int k0 = kc * 64;
#pragma unroll
    for (int j = 0; j < 4; j++) {
        const int gi = tid + j * 256;
        const int row = gi >> 3, g = gi & 7;
        const uint32_t soff = swz((uint32_t)(row * 128 + g * 16));
        const size_t ao = (size_t)(m0 + row) * SZ + k0 + g * 8;
        const size_t bo = (size_t)(n0 + row) * SZ + k0 + g * 8;
        cp16(base + OFF_AHI + soff, g_Xhi + ao);
        cp16(base + OFF_ALO + soff, g_Xlo + ao);
        cp16(base + OFF_BHI + soff, g_Gthi + bo);
        cp16(base + OFF_BLO + soff, g_Gtlo + bo);
    }
    asm volatile("cp.async.commit_group;" ::: "memory");
}

__global__ __launch_bounds__(256, 1)
void btt_gemm(const float* __restrict__ bias, float* __restrict__ out) {
    extern __shared__ char smem[];
    const uint32_t sb = smem_u32(smem);
    const int tid = threadIdx.x, wid = tid >> 5, lid = tid & 31;
    const int n0 = blockIdx.x * 128;   // N fastest -> G tiles stay hot in L2
    const int m0 = blockIdx.y * 128;
    const int warp_m = wid >> 2;       // 0..1  (64-row halves)
    const int warp_n = wid & 3;        // 0..3  (32-col slices)

    float acc[4][4][4];
#pragma unroll
    for (int i = 0; i < 4; i++)
#pragma unroll
        for (int j = 0; j < 4; j++)
#pragma unroll
            for (int k = 0; k < 4; k++) acc[i][j][k] = 0.f;

    issue_stage(sb, 0, 0, m0, n0, tid);
    issue_stage(sb, 1, 1, m0, n0, tid);

#pragma unroll 1
    for (int kc = 0; kc < NKITERS; kc++) {
        asm volatile("cp.async.wait_group 1;" ::: "memory");
        __syncthreads();
        if (kc + 2 < NKITERS) issue_stage(sb, (kc + 2) % NSTAGES, kc + 2, m0, n0, tid);

        const uint32_t base = sb + (uint32_t)(kc % NSTAGES) * STAGE_BYTES;
#pragma unroll
        for (int ks = 0; ks < 4; ks++) {        // k-steps of 16
            const int kb = ks * 32;             // bytes
            uint32_t ah[4][4], al[4][4], bh[8], bl[8];
#pragma unroll
            for (int mt = 0; mt < 4; mt++) {
                const int r0 = warp_m * 64 + mt * 16;
                LDSM4(ah[mt], lm_addr(base + OFF_AHI, lid, r0, kb));
                LDSM4(al[mt], lm_addr(base + OFF_ALO, lid, r0, kb));
            }
#pragma unroll
            for (int h = 0; h < 2; h++) {       // n-halves of 16 cols
                const int r0 = warp_n * 32 + h * 16;
                LDSM4(&bh[h * 4], lm_addr(base + OFF_BHI, lid, r0, kb));
                LDSM4(&bl[h * 4], lm_addr(base + OFF_BLO, lid, r0, kb));
            }
#pragma unroll
            for (int mt = 0; mt < 4; mt++)
#pragma unroll
                for (int nt = 0; nt < 4; nt++) {
                    const int i0 = (nt >> 1) * 4 + (nt & 1);   // b0 reg index
                    const int i1 = i0 + 2;                     // b1 reg index
                    MMA16816(acc[mt][nt], ah[mt], bh[i0], bh[i1]);
                    MMA16816(acc[mt][nt], ah[mt], bl[i0], bl[i1]);
                    MMA16816(acc[mt][nt], al[mt], bh[i0], bh[i1]);
                }
        }
    }

    // ---- epilogue: acc + bias -> out ----
    const int grp = lid >> 2, qid = lid & 3;
#pragma unroll
    for (int mt = 0; mt < 4; mt++) {
        const int mrow = m0 + warp_m * 64 + mt * 16 + grp;
#pragma unroll
        for (int nt = 0; nt < 4; nt++) {
            const int n = n0 + warp_n * 32 + nt * 8 + qid * 2;
            const float2 bv = *reinterpret_cast<const float2*>(bias + n);
            float2 v0, v1;
            v0.x = acc[mt][nt][0] + bv.x;
            v0.y = acc[mt][nt][1] + bv.y;
            v1.x = acc[mt][nt][2] + bv.x;
            v1.y = acc[mt][nt][3] + bv.y;
            *reinterpret_cast<float2*>(out + (size_t)mrow * SZ + n) = v0;
            *reinterpret_cast<float2*>(out + (size_t)(mrow + 8) * SZ + n) = v1;
        }
    }
}

// ================= launch =================
extern "C" void kernel_launch(void* const* d_in, const int* in_sizes, int n_in,
                              void* d_out, int out_size) {
    const float* x     = (const float*)d_in[0];
    const float* core0 = (const float*)d_in[1];
    const float* core1 = (const float*)d_in[2];
    const float* core2 = (const float*)d_in[3];
    const float* bias  = (const float*)d_in[4];
    float* out = (float*)d_out;

    build_gt<<<SZ, 256>>>(core0, core1, core2);
    split_x<<<(unsigned)(((size_t)NROWS * SZ + 255) / 256), 256>>>(x);

    static int smem_set = 0;
    if (!smem_set) {
        cudaFuncSetAttribute(btt_gemm, cudaFuncAttributeMaxDynamicSharedMemorySize, SM_TOTAL);
        smem_set = 1;
    }
    dim3 grid(SZ / 128, NROWS / 128);   // x = N tiles (32), y = M tiles (64)
    btt_gemm<<<grid, 256, SM_TOTAL>>>(bias, out);
}

// round 7
// speedup vs baseline: 1.4046x; 1.4046x over previous
#include <cuda_runtime.h>
#include <cuda_bf16.h>
#include <cstdint>
#include <cstddef>

#define SZ 4096
#define NROWS 8192

// -------- scratch (allocation-free rule: static __device__ arrays) --------
__device__ __nv_bfloat16 g_Xhi[(size_t)NROWS * SZ];   // 64 MB
__device__ __nv_bfloat16 g_Xlo[(size_t)NROWS * SZ];   // 64 MB
__device__ __nv_bfloat16 g_Ghi[(size_t)SZ * SZ];      // 32 MB  (row-major: [m][n], m = K dim)
__device__ __nv_bfloat16 g_Glo[(size_t)SZ * SZ];      // 32 MB

// ---------------- helpers ----------------
__device__ __forceinline__ uint32_t smem_u32(const void* p) {
    uint32_t a;
    asm("{ .reg .u64 t; cvta.to.shared.u64 t, %1; cvt.u32.u64 %0, t; }" : "=r"(a) : "l"(p));
    return a;
}
__device__ __forceinline__ uint32_t swz(uint32_t o) { return o ^ ((o >> 3) & 0x70); }

__device__ __forceinline__ void cp16(uint32_t dst, const void* src) {
    asm volatile("cp.async.cg.shared.global [%0], [%1], 16;" :: "r"(dst), "l"(src));
}

// ldmatrix x4 (non-transposed) — A operand, base-arch PTX (sm_75+)
#define LDSM4(r, addr)                                                             \
    asm volatile("ldmatrix.sync.aligned.m8n8.x4.shared.b16 {%0,%1,%2,%3}, [%4];"   \
                 : "=r"((r)[0]), "=r"((r)[1]), "=r"((r)[2]), "=r"((r)[3])          \
                 : "r"(addr))

// ldmatrix x4 transposed — B operand from [k][n] tiles
#define LDSM4T(r, addr)                                                            \
    asm volatile("ldmatrix.sync.aligned.m8n8.x4.trans.shared.b16 {%0,%1,%2,%3}, [%4];" \
                 : "=r"((r)[0]), "=r"((r)[1]), "=r"((r)[2]), "=r"((r)[3])          \
                 : "r"(addr))

// mma.sync m16n8k16 row.col f32.bf16.bf16.f32, base-arch PTX (sm_80+)
#define MMA16816(c, a, b0, b1)                                                     \
    asm volatile("mma.sync.aligned.m16n8k16.row.col.f32.bf16.bf16.f32 "            \
                 "{%0,%1,%2,%3}, {%4,%5,%6,%7}, {%8,%9}, {%0,%1,%2,%3};"           \
                 : "+f"((c)[0]), "+f"((c)[1]), "+f"((c)[2]), "+f"((c)[3])          \
                 : "r"((a)[0]), "r"((a)[1]), "r"((a)[2]), "r"((a)[3]),             \
                   "r"(b0), "r"(b1))

// A-tile lane address: 16(row)x16(k-col) region at (row0, kbyte0), rows 128B, SW128.
__device__ __forceinline__ uint32_t lm_addr(uint32_t base, int lane, int row0, int kbyte0) {
    const int r = row0 + (lane & 7) + ((lane >> 3) & 1) * 8;
    const int kb = kbyte0 + ((lane >> 4) << 4);
    return base + (uint32_t)(r * 128) + (uint32_t)(kb ^ ((r & 7) << 4));
}

// B-tile lane address for ldmatrix.trans: tile is [64 k-rows][128 n-cols] bf16,
// 256B rows, 16B-chunk c swizzled within each 128B half: c -> (c&8)|((c^k)&7).
// Lanes 0-15: k rows krow0..+15 at ncol0; lanes 16-31: same k rows at ncol0+8.
// -> matrices (k0-7,n0-7)(k8-15,n0-7)(k0-7,n8-15)(k8-15,n8-15); after .trans the
//    register pairs {r0,r1},{r2,r3} are exactly the mma B fragments for the two
//    8-col groups.
__device__ __forceinline__ uint32_t lmb_addr(uint32_t base, int lane, int krow0, int ncol0) {
    const int k = krow0 + (lane & 15);
    const int c = (ncol0 >> 3) + ((lane >> 4) & 1);
    return base + (uint32_t)(k * 256) + ((uint32_t)((c & 8) | ((c ^ k) & 7)) << 4);
}

// ================= kernel 1: build G (row-wise), row-major coalesced store =====
// G[m, n = y*256 + x*16 + z] = sum_B c2[m,z,B] * sum_b c1[m,x,B,b] * c0[m,y,b]
__global__ __launch_bounds__(256) void build_g(const float* __restrict__ core0,
                                               const float* __restrict__ core1,
                                               const float* __restrict__ core2) {
    __shared__ float c0s[128], c2s[128], c1s[1024];
    const int m = blockIdx.x;
    const int tid = threadIdx.x;
    if (tid < 128) {
        c0s[tid] = core0[m * 128 + tid];
        c2s[tid] = core2[m * 128 + tid];
    }
#pragma unroll
    for (int j = 0; j < 4; j++) c1s[tid + j * 256] = core1[m * 1024 + tid + j * 256];
    __syncthreads();

    const int y = tid >> 4, x = tid & 15;
    float a[8], Mr[8];
#pragma unroll
    for (int b = 0; b < 8; b++) a[b] = c0s[y * 8 + b];
#pragma unroll
    for (int B = 0; B < 8; B++) {
        float s = 0.f;
#pragma unroll
        for (int b = 0; b < 8; b++) s += c1s[x * 64 + B * 8 + b] * a[b];
        Mr[B] = s;
    }
    __nv_bfloat16 hb[16], lb[16];
#pragma unroll
    for (int z = 0; z < 16; z++) {
        float v = 0.f;
#pragma unroll
        for (int B = 0; B < 8; B++) v += Mr[B] * c2s[z * 8 + B];
        const __nv_bfloat16 h = __float2bfloat16(v);
        hb[z] = h;
        lb[z] = __float2bfloat16(v - __bfloat162float(h));
    }
    // thread's 16 z-values are contiguous: n = y*256 + x*16 + [0..16)
    const size_t o = (size_t)m * SZ + y * 256 + x * 16;
    *reinterpret_cast<uint4*>(g_Ghi + o)     = *reinterpret_cast<uint4*>(hb);
    *reinterpret_cast<uint4*>(g_Ghi + o + 8) = *reinterpret_cast<uint4*>(hb + 8);
    *reinterpret_cast<uint4*>(g_Glo + o)     = *reinterpret_cast<uint4*>(lb);
    *reinterpret_cast<uint4*>(g_Glo + o + 8) = *reinterpret_cast<uint4*>(lb + 8);
}

// ================= kernel 2: split X into bf16 hi/lo (float4 vectorized) ======
__global__ __launch_bounds__(256) void split_x(const float* __restrict__ x) {
    const size_t i4 = (size_t)blockIdx.x * 256 + threadIdx.x;   // float4 index
    const float4 v = reinterpret_cast<const float4*>(x)[i4];
    __nv_bfloat16 hb[4], lb[4];
    hb[0] = __float2bfloat16(v.x); lb[0] = __float2bfloat16(v.x - __bfloat162float(hb[0]));
    hb[1] = __float2bfloat16(v.y); lb[1] = __float2bfloat16(v.y - __bfloat162float(hb[1]));
    hb[2] = __float2bfloat16(v.z); lb[2] = __float2bfloat16(v.z - __bfloat162float(hb[2]));
    hb[3] = __float2bfloat16(v.w); lb[3] = __float2bfloat16(v.w - __bfloat162float(hb[3]));
    *reinterpret_cast<uint2*>(g_Xhi + 4 * i4) = *reinterpret_cast<uint2*>(hb);
    *reinterpret_cast<uint2*>(g_Xlo + 4 * i4) = *reinterpret_cast<uint2*>(lb);
}

// ================= kernel 3: split-bf16 mma.sync GEMM + bias =================
// out[8192,4096] = Xhi@Ghi + Xhi@Glo + Xlo@Ghi + bias   (fp32 register accum)
// CTA tile 128x128, BK=64, 3-stage cp.async pipeline.
// A tiles: [128 m][64 k] K-major 128B rows, SW128.  B tiles: [64 k][128 n] 256B rows.
#define STAGE_BYTES 65536
#define OFF_AHI 0
#define OFF_ALO 16384
#define OFF_BHI 32768
#define OFF_BLO 49152
#define NSTAGES 3
#define SM_TOTAL (NSTAGES * STAGE_BYTES)
#define NKITERS 64   // 4096 / 64

__device__ __forceinline__ void issue_stage(uint32_t sb, int stage, int kc,
                                            int m0, int n0, int tid) {
    const uint32_t base = sb + (uint32_t)stage * STAGE_BYTES;
    const int k0 = kc * 64;
#pragma unroll
    for (int j = 0; j < 4; j++) {
        const int gi = tid + j * 256;
        // ---- A: X K-major, 1024 chunks = 128 rows x 8 chunks(16B) ----
        const int rowA = gi >> 3, gA = gi & 7;
        const uint32_t offA = swz((uint32_t)(rowA * 128 + gA * 16));
        const size_t ao = (size_t)(m0 + rowA) * SZ + k0 + gA * 8;
        cp16(base + OFF_AHI + offA, g_Xhi + ao);
        cp16(base + OFF_ALO + offA, g_Xlo + ao);
        // ---- B: G row-major [k][n], 1024 chunks = 64 rows x 16 chunks(16B) ----
        const int kB = gi >> 4, cB = gi & 15;
        const uint32_t offB = (uint32_t)(kB * 256) +
                              ((uint32_t)((cB & 8) | ((cB ^ kB) & 7)) << 4);
        const size_t bo = (size_t)(k0 + kB) * SZ + n0 + cB * 8;
        cp16(base + OFF_BHI + offB, g_Ghi + bo);
        cp16(base + OFF_BLO + offB, g_Glo + bo);
    }
    asm volatile("cp.async.commit_group;" ::: "memory");
}

__global__ __launch_bounds__(256, 1)
void btt_gemm(const float* __restrict__ bias, float* __restrict__ out) {
    extern __shared__ char smem[];
    const uint32_t sb = smem_u32(smem);
    const int tid = threadIdx.x, wid = tid >> 5, lid = tid & 31;
    const int n0 = blockIdx.x * 128;   // N fastest -> G tiles stay hot in L2
    const int m0 = blockIdx.y * 128;
    const int warp_m = wid >> 2;       // 0..1  (64-row halves)
    const int warp_n = wid & 3;        // 0..3  (32-col slices)

    float acc[4][4][4];
#pragma unroll
    for (int i = 0; i < 4; i++)
#pragma unroll
        for (int j = 0; j < 4; j++)
#pragma unroll
            for (int k = 0; k < 4; k++) acc[i][j][k] = 0.f;

    issue_stage(sb, 0, 0, m0, n0, tid);
    issue_stage(sb, 1, 1, m0, n0, tid);

#pragma unroll 1
    for (int kc = 0; kc < NKITERS; kc++) {
        asm volatile("cp.async.wait_group 1;" ::: "memory");
        __syncthreads();
        if (kc + 2 < NKITERS) issue_stage(sb, (kc + 2) % NSTAGES, kc + 2, m0, n0, tid);

        const uint32_t base = sb + (uint32_t)(kc % NSTAGES) * STAGE_BYTES;
#pragma unroll
        for (int ks = 0; ks < 4; ks++) {        // k-steps of 16
            const int kb = ks * 32;             // A k-offset in bytes
            uint32_t ah[4][4], al[4][4], bh[8], bl[8];
#pragma unroll
            for (int mt = 0; mt < 4; mt++) {
                const int r0 = warp_m * 64 + mt * 16;
                LDSM4(ah[mt], lm_addr(base + OFF_AHI, lid, r0, kb));
                LDSM4(al[mt], lm_addr(base + OFF_ALO, lid, r0, kb));
            }
#pragma unroll
            for (int h = 0; h < 2; h++) {       // n-halves of 16 cols
                const int nc = warp_n * 32 + h * 16;
                LDSM4T(&bh[h * 4], lmb_addr(base + OFF_BHI, lid, ks * 16, nc));
                LDSM4T(&bl[h * 4], lmb_addr(base + OFF_BLO, lid, ks * 16, nc));
            }
            // product-outermost: 16 independent accumulators between RAW reuses
#pragma unroll
            for (int mt = 0; mt < 4; mt++)
#pragma unroll
                for (int nt = 0; nt < 4; nt++) {
                    const int i0 = (nt >> 1) * 4 + (nt & 1) * 2;
                    MMA16816(acc[mt][nt], ah[mt], bh[i0], bh[i0 + 1]);
                }
#pragma unroll
            for (int mt = 0; mt < 4; mt++)
#pragma unroll
                for (int nt = 0; nt < 4; nt++) {
                    const int i0 = (nt >> 1) * 4 + (nt & 1) * 2;
                    MMA16816(acc[mt][nt], ah[mt], bl[i0], bl[i0 + 1]);
                }
#pragma unroll
            for (int mt = 0; mt < 4; mt++)
#pragma unroll
                for (int nt = 0; nt < 4; nt++) {
                    const int i0 = (nt >> 1) * 4 + (nt & 1) * 2;
                    MMA16816(acc[mt][nt], al[mt], bh[i0], bh[i0 + 1]);
                }
        }
    }

    // ---- epilogue: acc + bias -> out ----
    const int grp = lid >> 2, qid = lid & 3;
#pragma unroll
    for (int mt = 0; mt < 4; mt++) {
        const int mrow = m0 + warp_m * 64 + mt * 16 + grp;
#pragma unroll
        for (int nt = 0; nt < 4; nt++) {
            const int n = n0 + warp_n * 32 + nt * 8 + qid * 2;
            const float2 bv = *reinterpret_cast<const float2*>(bias + n);
            float2 v0, v1;
            v0.x = acc[mt][nt][0] + bv.x;
            v0.y = acc[mt][nt][1] + bv.y;
            v1.x = acc[mt][nt][2] + bv.x;
            v1.y = acc[mt][nt][3] + bv.y;
            *reinterpret_cast<float2*>(out + (size_t)mrow * SZ + n) = v0;
            *reinterpret_cast<float2*>(out + (size_t)(mrow + 8) * SZ + n) = v1;
        }
    }
}

// ================= launch =================
extern "C" void kernel_launch(void* const* d_in, const int* in_sizes, int n_in,
                              void* d_out, int out_size) {
    const float* x     = (const float*)d_in[0];
    const float* core0 = (const float*)d_in[1];
    const float* core1 = (const float*)d_in[2];
    const float* core2 = (const float*)d_in[3];
    const float* bias  = (const float*)d_in[4];
    float* out = (float*)d_out;

    build_g<<<SZ, 256>>>(core0, core1, core2);
    split_x<<<(unsigned)(((size_t)NROWS * SZ) / (4 * 256)), 256>>>(x);

    static int smem_set = 0;
    if (!smem_set) {
        cudaFuncSetAttribute(btt_gemm, cudaFuncAttributeMaxDynamicSharedMemorySize, SM_TOTAL);
        smem_set = 1;
    }
    dim3 grid(SZ / 128, NROWS / 128);   // x = N tiles (32), y = M tiles (64)
    btt_gemm<<<grid, 256, SM_TOTAL>>>(bias, out);
}